// round 15
// baseline (speedup 1.0000x reference)
#include <cuda_runtime.h>
#include <math.h>

typedef unsigned long long u64;
#define DEV static __device__ __forceinline__

// ---------------- packed f32x2 helpers ----------------
DEV void fma2(u64 &d, u64 a, u64 b) {
    asm("fma.rn.f32x2 %0, %1, %2, %0;" : "+l"(d) : "l"(a), "l"(b));
}
DEV u64 bcast2(float x) {
    u64 r; asm("mov.b64 %0, {%1, %1};" : "=l"(r) : "f"(x)); return r;
}
DEV u64 pack2(float lo, float hi) {
    u64 r; asm("mov.b64 %0, {%1, %2};" : "=l"(r) : "f"(lo), "f"(hi)); return r;
}
DEV void unpack2(u64 v, float &a, float &b) {
    asm("mov.b64 {%0, %1}, %2;" : "=f"(a), "=f"(b) : "l"(v));
}

// ---------------- scratch (static device memory; no runtime allocs) ------
__device__ float g_h1 [16*64*128*128];   // encoder conv1 out
__device__ float g_h2 [16*128*64*64];    // encoder conv2 out
__device__ float g_h3 [16*128*64*64];    // conv3 / resblock io
__device__ float g_t32[16*32*64*64];     // resblock mid
__device__ float g_z  [16*64*64*64];     // pre-VQ latents, NHWC (pixel-major)
__device__ float g_d1 [16*128*64*64];    // decoder 128ch buffer
__device__ float g_dt1[16*64*128*128];   // convT1 out
__device__ float g_cnorm[512];
__device__ float g_bsums[256];
__device__ int   g_counts[512];

// ======================================================================
// conv1: x(16,1,256,256) -> h1(16,64,128,128), 4x4 s2 p1, bias+ReLU
// (unchanged — bit-exact encoder path)
// ======================================================================
__global__ void __launch_bounds__(256) k_conv1(
    const float* __restrict__ x, const float* __restrict__ w,
    const float* __restrict__ bias, float* __restrict__ out)
{
    const int X = threadIdx.x;
    const int Y = blockIdx.x * 2 + threadIdx.y;
    const int n = blockIdx.y;
    const int tid = threadIdx.y * 128 + X;

    __shared__ __align__(16) float ws[16 * 64];   // [tap][oc]
    for (int i = tid; i < 1024; i += 256) {
        int oc = i & 63, tap = i >> 6;
        ws[tap * 64 + oc] = w[oc * 16 + tap];
    }
    __syncthreads();

    u64 acc[32];
#pragma unroll
    for (int i = 0; i < 32; i++) acc[i] = 0ull;

    const float* xin = x + (size_t)n * 65536;
#pragma unroll
    for (int dy = 0; dy < 4; dy++) {
        int iy = 2 * Y + dy - 1;
        bool yv = (unsigned)iy < 256u;
#pragma unroll
        for (int dx = 0; dx < 4; dx++) {
            int ix = 2 * X + dx - 1;
            float v = (yv && (unsigned)ix < 256u) ? xin[iy * 256 + ix] : 0.f;
            u64 vb = bcast2(v);
            const ulonglong2* wp = (const ulonglong2*)&ws[(dy * 4 + dx) * 64];
#pragma unroll
            for (int j = 0; j < 16; j++) {
                ulonglong2 wv = wp[j];
                fma2(acc[2*j],   vb, wv.x);
                fma2(acc[2*j+1], vb, wv.y);
            }
        }
    }
    float* o = out + (((size_t)n * 64) * 128 + Y) * 128 + X;
#pragma unroll
    for (int j = 0; j < 32; j++) {
        float a, b; unpack2(acc[j], a, b);
        a = fmaxf(a + bias[2*j],   0.f);
        b = fmaxf(b + bias[2*j+1], 0.f);
        o[(2*j)   * 16384] = a;
        o[(2*j+1) * 16384] = b;
    }
}

// ======================================================================
// conv2: h1(16,64,128,128) -> h2(16,128,64,64), 4x4 s2 p1, bias+ReLU
// 2x2 output px per thread, OC_T=8.  blockDim(32,8)  grid(4, 16, 16)
// (kept from R14 — net-improving side of that round)
// ======================================================================
__global__ void __launch_bounds__(256, 2) k_conv2(
    const float* __restrict__ in, const float* __restrict__ w,
    const float* __restrict__ bias, float* __restrict__ out)
{
    const int tx = threadIdx.x;                 // 0..31
    const int ty = threadIdx.y;                 // 0..7
    const int X0 = tx * 2;
    const int Y0 = blockIdx.x * 16 + ty * 2;
    const int ocB = blockIdx.y * 8;
    const int n = blockIdx.z;
    const int tid = ty * 32 + tx;

    __shared__ __align__(16) float ws[16 * 16 * 8];   // [cc][tap][oc8] = 2048

    u64 acc[4][4];                               // [qy*2+qx][oc-pair]
#pragma unroll
    for (int i = 0; i < 4; i++)
#pragma unroll
        for (int j = 0; j < 4; j++) acc[i][j] = 0ull;

    for (int cib = 0; cib < 64; cib += 16) {
        __syncthreads();
#pragma unroll
        for (int i = 0; i < 8; i++) {
            int idx = tid + i * 256;
            int oc = idx & 7, tap = (idx >> 3) & 15, cc = idx >> 7;
            ws[idx] = w[((ocB + oc) * 64 + cib + cc) * 16 + tap];
        }
        __syncthreads();
#pragma unroll 2
        for (int cc = 0; cc < 16; cc++) {
            const float* p = in + (size_t)(n * 64 + cib + cc) * 16384;
#pragma unroll
            for (int r = 0; r < 6; r++) {
                int iy = 2 * Y0 - 1 + r;
                bool yv = (unsigned)iy < 128u;
                const float* row = p + iy * 128 + 2 * X0 - 1;
                u64 vbr[6];
#pragma unroll
                for (int c = 0; c < 6; c++) {
                    int ix = 2 * X0 - 1 + c;
                    float v = (yv && (unsigned)ix < 128u) ? row[c] : 0.f;
                    vbr[c] = bcast2(v);
                }
#pragma unroll
                for (int qy = 0; qy < 2; qy++) {
                    int dy = r - 2 * qy;
                    if (dy < 0 || dy > 3) continue;
#pragma unroll
                    for (int dx = 0; dx < 4; dx++) {
                        const ulonglong2* wp = (const ulonglong2*)&ws[(cc * 16 + dy * 4 + dx) * 8];
                        ulonglong2 w0 = wp[0], w1 = wp[1];
#pragma unroll
                        for (int qx = 0; qx < 2; qx++) {
                            u64 b = vbr[dx + 2 * qx];
                            fma2(acc[qy*2+qx][0], b, w0.x);
                            fma2(acc[qy*2+qx][1], b, w0.y);
                            fma2(acc[qy*2+qx][2], b, w1.x);
                            fma2(acc[qy*2+qx][3], b, w1.y);
                        }
                    }
                }
            }
        }
    }
    float* o = out + ((size_t)(n * 128 + ocB)) * 4096 + Y0 * 64 + X0;
#pragma unroll
    for (int j = 0; j < 4; j++) {
        float q0 = bias[ocB + 2*j], q1 = bias[ocB + 2*j+1];
#pragma unroll
        for (int qy = 0; qy < 2; qy++)
#pragma unroll
            for (int qx = 0; qx < 2; qx++) {
                float a, b; unpack2(acc[qy*2+qx][j], a, b);
                o[(2*j)   * 4096 + qy * 64 + qx] = fmaxf(a + q0, 0.f);
                o[(2*j+1) * 4096 + qy * 64 + qx] = fmaxf(b + q1, 0.f);
            }
    }
}

// ======================================================================
// generic 3x3 conv on 64x64, stride1 pad1.
// 2 ADJACENT rows per thread (Y0, Y0+1) -> rows shared, unit-stride LDG:
// 12 LDG / cc (vs 18 in R12, vs 16 strided in R14).  OC_T=16.
// blockDim(64,4)  grid(8, COUT/16, 16)
// Per-output tap order: cib asc, cc asc, (r,s) asc — bit-exact vs R9/R12.
// ======================================================================
template<int CIN, int COUT, bool RELU_IN, bool HAS_BIAS>
__global__ void __launch_bounds__(256, 2) k_conv3x3(
    const float* __restrict__ in, const float* __restrict__ w,
    const float* __restrict__ bias, float* __restrict__ out)
{
    const int X = threadIdx.x;                       // 0..63 unit stride
    const int Y0 = blockIdx.x * 8 + threadIdx.y * 2; // rows Y0, Y0+1
    const int ocB = blockIdx.y * 16;
    const int n = blockIdx.z;
    const int tid = threadIdx.y * 64 + X;

    __shared__ __align__(16) float ws[32 * 9 * 16];  // [cc][tap][oc16] = 4608

    u64 a0[8], a1[8];
#pragma unroll
    for (int i = 0; i < 8; i++) { a0[i] = 0ull; a1[i] = 0ull; }

    const bool xm = (X > 0), xp = (X < 63);
    for (int cib = 0; cib < CIN; cib += 32) {
        __syncthreads();
#pragma unroll
        for (int i = 0; i < 18; i++) {
            int idx = tid + i * 256;                 // < 4608
            int oc = idx & 15;
            int r  = idx >> 4;
            int tap = r % 9;
            int cc = r / 9;
            ws[(cc * 9 + tap) * 16 + oc] = w[((ocB + oc) * CIN + cib + cc) * 9 + tap];
        }
        __syncthreads();
#pragma unroll 2
        for (int cc = 0; cc < 32; cc++) {
            const float* p = in + (size_t)(n * CIN + cib + cc) * 4096;
            u64 vb[4][3];                            // rows Y0-1..Y0+2, cols X-1..X+1
#pragma unroll
            for (int r = 0; r < 4; r++) {
                int iy = Y0 - 1 + r;
                bool yv = (unsigned)iy < 64u;
                const float* row = p + iy * 64 + X;
                float f0 = (yv && xm) ? row[-1] : 0.f;
                float f1 =  yv        ? row[0]  : 0.f;
                float f2 = (yv && xp) ? row[1]  : 0.f;
                if (RELU_IN) {
                    f0 = fmaxf(f0, 0.f); f1 = fmaxf(f1, 0.f); f2 = fmaxf(f2, 0.f);
                }
                vb[r][0] = bcast2(f0);
                vb[r][1] = bcast2(f1);
                vb[r][2] = bcast2(f2);
            }
#pragma unroll
            for (int r = 0; r < 3; r++) {
#pragma unroll
                for (int s = 0; s < 3; s++) {
                    const ulonglong2* wp = (const ulonglong2*)&ws[(cc * 9 + r * 3 + s) * 16];
                    u64 b0 = vb[r][s];               // pixel row Y0
                    u64 b1 = vb[r + 1][s];           // pixel row Y0+1
#pragma unroll
                    for (int j = 0; j < 4; j++) {
                        ulonglong2 wv = wp[j];
                        fma2(a0[2*j],   b0, wv.x);
                        fma2(a0[2*j+1], b0, wv.y);
                        fma2(a1[2*j],   b1, wv.x);
                        fma2(a1[2*j+1], b1, wv.y);
                    }
                }
            }
        }
    }
    float* o0 = out + ((size_t)(n * COUT + ocB)) * 4096 + Y0 * 64 + X;
    float* o1 = o0 + 64;
#pragma unroll
    for (int j = 0; j < 8; j++) {
        float a, b; unpack2(a0[j], a, b);
        float c, d; unpack2(a1[j], c, d);
        if (HAS_BIAS) {
            float q0 = bias[ocB + 2*j], q1 = bias[ocB + 2*j+1];
            a += q0; b += q1; c += q0; d += q1;
        }
        o0[(2*j)   * 4096] = a;
        o0[(2*j+1) * 4096] = b;
        o1[(2*j)   * 4096] = c;
        o1[(2*j+1) * 4096] = d;
    }
}

// ======================================================================
// generic 1x1 conv on 64x64.  2 px/thread, OC_T=32. (unchanged)
// blockDim(64,4)  grid(8, COUT/32, 16)
// ======================================================================
template<int CIN, int COUT, bool RELU_IN, bool HAS_BIAS, bool RESID, bool NHWC_OUT>
__global__ void __launch_bounds__(256, 2) k_conv1x1(
    const float* __restrict__ in, const float* __restrict__ w,
    const float* __restrict__ bias, const float* __restrict__ resid,
    float* __restrict__ out)
{
    const int X = threadIdx.x;
    const int Y0 = blockIdx.x * 8 + threadIdx.y;   // rows Y0, Y0+4
    const int ocB = blockIdx.y * 32;
    const int n = blockIdx.z;
    const int tid = threadIdx.y * 64 + X;

    __shared__ __align__(16) float ws[CIN * 32];
    for (int i = tid; i < CIN * 32; i += 256) {
        int oc = i & 31, c = i >> 5;
        ws[i] = w[(ocB + oc) * CIN + c];
    }
    __syncthreads();

    u64 a0[16], a1[16];
#pragma unroll
    for (int i = 0; i < 16; i++) { a0[i] = 0ull; a1[i] = 0ull; }

    const float* p0 = in + (size_t)n * CIN * 4096 + Y0 * 64 + X;
    const float* p1 = p0 + 4 * 64;
#pragma unroll 4
    for (int c = 0; c < CIN; c++) {
        float v0 = p0[c * 4096];
        float v1 = p1[c * 4096];
        if (RELU_IN) { v0 = fmaxf(v0, 0.f); v1 = fmaxf(v1, 0.f); }
        u64 b0 = bcast2(v0), b1 = bcast2(v1);
        const ulonglong2* wp = (const ulonglong2*)&ws[c * 32];
#pragma unroll
        for (int j = 0; j < 8; j++) {
            ulonglong2 wv = wp[j];
            fma2(a0[2*j],   b0, wv.x);
            fma2(a0[2*j+1], b0, wv.y);
            fma2(a1[2*j],   b1, wv.x);
            fma2(a1[2*j+1], b1, wv.y);
        }
    }
    if (NHWC_OUT) {
        float* o0 = out + ((size_t)((n * 64 + Y0) * 64 + X)) * COUT + ocB;
        float* o1 = o0 + (size_t)4 * 64 * COUT;
#pragma unroll
        for (int j = 0; j < 16; j++) {
            float a, b; unpack2(a0[j], a, b);
            float c, d; unpack2(a1[j], c, d);
            if (HAS_BIAS) {
                float q0 = bias[ocB + 2*j], q1 = bias[ocB + 2*j+1];
                a += q0; b += q1; c += q0; d += q1;
            }
            o0[2*j] = a; o0[2*j+1] = b;
            o1[2*j] = c; o1[2*j+1] = d;
        }
    } else {
        float* o0 = out + ((size_t)(n * COUT + ocB)) * 4096 + Y0 * 64 + X;
        float* o1 = o0 + 4 * 64;
        const float* r0 = RESID ? resid + ((size_t)(n * COUT + ocB)) * 4096 + Y0 * 64 + X : (const float*)0;
        const float* r1 = RESID ? r0 + 4 * 64 : (const float*)0;
#pragma unroll
        for (int j = 0; j < 16; j++) {
            float a, b; unpack2(a0[j], a, b);
            float c, d; unpack2(a1[j], c, d);
            if (HAS_BIAS) {
                float q0 = bias[ocB + 2*j], q1 = bias[ocB + 2*j+1];
                a += q0; b += q1; c += q0; d += q1;
            }
            if (RESID) {
                a += r0[(2*j) * 4096]; b += r0[(2*j+1) * 4096];
                c += r1[(2*j) * 4096]; d += r1[(2*j+1) * 4096];
            }
            o0[(2*j)   * 4096] = a;
            o0[(2*j+1) * 4096] = b;
            o1[(2*j)   * 4096] = c;
            o1[(2*j+1) * 4096] = d;
        }
    }
}

// ======================================================================
// XLA-GPU-style 64-element fp32 row sum of squares (reference-matching).
// ======================================================================
DEV float rowsumsq64(const float* __restrict__ x) {
    float p[32];
#pragma unroll
    for (int t = 0; t < 32; t++) {
        float m0 = __fmul_rn(x[2*t],   x[2*t]);
        float m1 = __fmul_rn(x[2*t+1], x[2*t+1]);
        p[t] = __fadd_rn(m0, m1);
    }
#pragma unroll
    for (int off = 16; off >= 1; off >>= 1) {
#pragma unroll
        for (int t = 0; t < 16; t++)
            if (t < off) p[t] = __fadd_rn(p[t], p[t + off]);
    }
    return p[0];
}

// ======================================================================
// VQ prep: codebook norms + zero reductions.  <<<1,512>>>
// ======================================================================
__global__ void k_vq_prep(const float* __restrict__ cb) {
    int t = threadIdx.x;
    float row[64];
    const float4* rp = (const float4*)(cb + t * 64);
#pragma unroll
    for (int i = 0; i < 16; i++) {
        float4 v = rp[i];
        row[4*i] = v.x; row[4*i+1] = v.y; row[4*i+2] = v.z; row[4*i+3] = v.w;
    }
    g_cnorm[t] = rowsumsq64(row);
    g_counts[t] = 0;
    if (t < 256) g_bsums[t] = 0.f;
}

// ======================================================================
// VQ main: one thread per pixel.  <<<256, 256>>>
// ======================================================================
__global__ void __launch_bounds__(256) k_vq(
    const float* __restrict__ cb, float* __restrict__ qout,
    float* __restrict__ enc)
{
    const int p = blockIdx.x * 256 + threadIdx.x;
    const int t = threadIdx.x;
    __shared__ __align__(16) float cbs[64 * 64];
    __shared__ float cns[64];
    __shared__ int hist[512];
    __shared__ float red[256];
    for (int i = t; i < 512; i += 256) hist[i] = 0;

    u64 zv[32];
    float zz;
    {
        float zrow[64];
        const float4* zp = (const float4*)(g_z + (size_t)p * 64);
#pragma unroll
        for (int i = 0; i < 16; i++) {
            float4 z4 = zp[i];
            zrow[4*i] = z4.x; zrow[4*i+1] = z4.y; zrow[4*i+2] = z4.z; zrow[4*i+3] = z4.w;
            zv[2*i]   = pack2(z4.x, z4.y);
            zv[2*i+1] = pack2(z4.z, z4.w);
        }
        zz = rowsumsq64(zrow);
    }

    float best = 3.4e38f; int bk = 0;
    for (int kb = 0; kb < 512; kb += 64) {
        __syncthreads();
        for (int i = t; i < 64 * 64; i += 256) cbs[i] = cb[kb * 64 + i];
        if (t < 64) cns[t] = g_cnorm[kb + t];
        __syncthreads();
#pragma unroll 2
        for (int kk = 0; kk < 64; kk++) {
            u64 s0 = 0ull, s1 = 0ull;
            const ulonglong2* cp = (const ulonglong2*)&cbs[kk * 64];
#pragma unroll
            for (int j = 0; j < 16; j++) {
                ulonglong2 cw = cp[j];
                fma2(s0, zv[2*j],   cw.x);
                fma2(s1, zv[2*j+1], cw.y);
            }
            float a, b, c, d; unpack2(s0, a, b); unpack2(s1, c, d);
            float dot = (a + b) + (c + d);
            float dist = __fsub_rn(__fadd_rn(zz, cns[kk]), 2.0f * dot);
            if (dist < best) { best = dist; bk = kb + kk; }
        }
    }

    const float* q = cb + bk * 64;
    const int n = p >> 12;
    const int yx = p & 4095;
    float* qo = qout + (size_t)n * 64 * 4096 + yx;
    float sse = 0.f;
#pragma unroll
    for (int i = 0; i < 16; i++) {
        float4 qv = ((const float4*)q)[i];
        float z0, z1, z2, z3;
        unpack2(zv[2*i], z0, z1); unpack2(zv[2*i+1], z2, z3);
        float d0 = qv.x - z0, d1 = qv.y - z1, d2 = qv.z - z2, d3 = qv.w - z3;
        sse += d0*d0 + d1*d1 + d2*d2 + d3*d3;
        qo[(4*i)   * 4096] = qv.x;
        qo[(4*i+1) * 4096] = qv.y;
        qo[(4*i+2) * 4096] = qv.z;
        qo[(4*i+3) * 4096] = qv.w;
    }
    enc[(size_t)p * 512 + bk] = 1.0f;
    atomicAdd(&hist[bk], 1);
    red[t] = sse;
    __syncthreads();
    for (int s = 128; s > 0; s >>= 1) {
        if (t < s) red[t] += red[t + s];
        __syncthreads();
    }
    if (t == 0) g_bsums[blockIdx.x] = red[0];
    for (int i = t; i < 512; i += 256)
        if (hist[i]) atomicAdd(&g_counts[i], hist[i]);
}

// ======================================================================
// finalize: loss + perplexity scalars
// ======================================================================
__global__ void k_finalize(float* __restrict__ out_loss, float* __restrict__ out_perp) {
    if (threadIdx.x == 0) {
        float s = 0.f;
        for (int i = 0; i < 256; i++) s += g_bsums[i];
        out_loss[0] = 1.25f * s / (65536.f * 64.f);
        float h = 0.f;
        for (int k = 0; k < 512; k++) {
            float avg = (float)g_counts[k] / 65536.f;
            h += avg * logf(avg + 1e-10f);
        }
        out_perp[0] = expf(-h);
    }
}

// ======================================================================
// convT1: d1(16,128,64,64) -> dt1(16,64,128,128), 4x4 s2 p1, bias+ReLU
// same-parity 2x2 px/thread (shares 4 taps + 3x3 input patch), OC_T=8.
// blockDim(64,4)  grid(16, 8, 16)   (kept from R14)
// ======================================================================
__global__ void __launch_bounds__(256, 2) k_convT1(
    const float* __restrict__ in, const float* __restrict__ w,
    const float* __restrict__ bias, float* __restrict__ out)
{
    const int tx = threadIdx.x;                       // 0..63
    const int X0 = (tx & 1) | ((tx >> 1) << 2);       // cols X0, X0+2
    const int vv = blockIdx.x * 4 + threadIdx.y;      // 0..63
    const int Y0 = (vv & 1) | ((vv >> 1) << 2);       // rows Y0, Y0+2
    const int ocB = blockIdx.y * 8;
    const int n = blockIdx.z;
    const int tid = threadIdx.y * 64 + tx;

    __shared__ __align__(16) float ws[16 * 16 * 8];   // [cc][tap][oc8] = 2048

    int ys0, tys0, tys1;      // ys1 = ys0 - 1
    if (Y0 & 1) { ys0 = (Y0 + 1) >> 1; tys0 = 0; tys1 = 2; }
    else        { ys0 =  Y0      >> 1; tys0 = 1; tys1 = 3; }
    int xs0, txs0, txs1;      // xs1 = xs0 - 1
    if (X0 & 1) { xs0 = (X0 + 1) >> 1; txs0 = 0; txs1 = 2; }
    else        { xs0 =  X0      >> 1; txs0 = 1; txs1 = 3; }
    const int tys[2] = { tys0, tys1 };
    const int txs[2] = { txs0, txs1 };
    const int rbase = ys0 - 1;   // input rows rbase..rbase+2
    const int cbase = xs0 - 1;   // input cols cbase..cbase+2

    u64 acc[4][4];
#pragma unroll
    for (int i = 0; i < 4; i++)
#pragma unroll
        for (int j = 0; j < 4; j++) acc[i][j] = 0ull;

    for (int cib = 0; cib < 128; cib += 16) {
        __syncthreads();
#pragma unroll
        for (int i = 0; i < 8; i++) {
            int idx = tid + i * 256;
            int oc = idx & 7, tap = (idx >> 3) & 15, cc = idx >> 7;
            ws[idx] = w[((cib + cc) * 64 + ocB + oc) * 16 + tap];
        }
        __syncthreads();
#pragma unroll 2
        for (int cc = 0; cc < 16; cc++) {
            const float* p = in + (size_t)(n * 128 + cib + cc) * 4096;
            u64 vb[3][3];
#pragma unroll
            for (int r = 0; r < 3; r++) {
                int iy = rbase + r;
                bool yv = (unsigned)iy < 64u;
#pragma unroll
                for (int c = 0; c < 3; c++) {
                    int ix = cbase + c;
                    float v = (yv && (unsigned)ix < 64u) ? p[iy * 64 + ix] : 0.f;
                    vb[r][c] = bcast2(v);
                }
            }
#pragma unroll
            for (int a = 0; a < 2; a++) {
#pragma unroll
                for (int b = 0; b < 2; b++) {
                    int tap = tys[a] * 4 + txs[b];
                    const ulonglong2* wp = (const ulonglong2*)&ws[(cc * 16 + tap) * 8];
                    ulonglong2 w0 = wp[0], w1 = wp[1];
#pragma unroll
                    for (int qy = 0; qy < 2; qy++) {
#pragma unroll
                        for (int qx = 0; qx < 2; qx++) {
                            u64 bv = vb[1 - a + qy][1 - b + qx];
                            fma2(acc[qy*2+qx][0], bv, w0.x);
                            fma2(acc[qy*2+qx][1], bv, w0.y);
                            fma2(acc[qy*2+qx][2], bv, w1.x);
                            fma2(acc[qy*2+qx][3], bv, w1.y);
                        }
                    }
                }
            }
        }
    }
    float* o = out + ((size_t)(n * 64 + ocB)) * 16384 + Y0 * 128 + X0;
#pragma unroll
    for (int j = 0; j < 4; j++) {
        float q0 = bias[ocB + 2*j], q1 = bias[ocB + 2*j+1];
#pragma unroll
        for (int qy = 0; qy < 2; qy++)
#pragma unroll
            for (int qx = 0; qx < 2; qx++) {
                float a, b; unpack2(acc[qy*2+qx][j], a, b);
                o[(2*j)   * 16384 + qy * 2 * 128 + qx * 2] = fmaxf(a + q0, 0.f);
                o[(2*j+1) * 16384 + qy * 2 * 128 + qx * 2] = fmaxf(b + q1, 0.f);
            }
    }
}

// ======================================================================
// convT2: dt1(16,64,128,128) -> x_rec(16,1,256,256), 4x4 s2 p1, bias
// ======================================================================
__global__ void __launch_bounds__(256) k_convT2(
    const float* __restrict__ in, const float* __restrict__ w,
    const float* __restrict__ bias, float* __restrict__ out)
{
    const int X = threadIdx.x;
    const int Y = blockIdx.x;
    const int n = blockIdx.y;
    __shared__ float ws[1024];   // [tap][ci]
    for (int i = X; i < 1024; i += 256) {
        int tp = i >> 6, ci = i & 63;
        ws[tp * 64 + ci] = w[ci * 16 + tp];
    }
    __syncthreads();

    int ys[2], tys[2], xs[2], txs[2];
    if (Y & 1) { ys[0] = (Y+1) >> 1; tys[0] = 0; ys[1] = (Y-1) >> 1; tys[1] = 2; }
    else       { ys[0] =  Y    >> 1; tys[0] = 1; ys[1] = (Y-2) >> 1; tys[1] = 3; }
    if (X & 1) { xs[0] = (X+1) >> 1; txs[0] = 0; xs[1] = (X-1) >> 1; txs[1] = 2; }
    else       { xs[0] =  X    >> 1; txs[0] = 1; xs[1] = (X-2) >> 1; txs[1] = 3; }

    float acc = bias[0];
#pragma unroll
    for (int a = 0; a < 2; a++) {
        if ((unsigned)ys[a] >= 128u) continue;
#pragma unroll
        for (int b = 0; b < 2; b++) {
            if ((unsigned)xs[b] >= 128u) continue;
            const float* p = in + (size_t)n * 1048576 + ys[a] * 128 + xs[b];
            const float* wr = &ws[(tys[a] * 4 + txs[b]) * 64];
            float s = 0.f;
#pragma unroll 16
            for (int ci = 0; ci < 64; ci++) s += p[ci * 16384] * wr[ci];
            acc += s;
        }
    }
    out[(size_t)n * 65536 + Y * 256 + X] = acc;
}

// ======================================================================
// kernel_launch
// ======================================================================
extern "C" void kernel_launch(void* const* d_in, const int* in_sizes, int n_in,
                              void* d_out, int out_size)
{
    (void)in_sizes; (void)n_in; (void)out_size;
    const float* x    = (const float*)d_in[0];
    const float* ew1  = (const float*)d_in[1];
    const float* eb1  = (const float*)d_in[2];
    const float* ew2  = (const float*)d_in[3];
    const float* eb2  = (const float*)d_in[4];
    const float* ew3  = (const float*)d_in[5];
    const float* eb3  = (const float*)d_in[6];
    const float* er1a = (const float*)d_in[7];
    const float* er1b = (const float*)d_in[8];
    const float* er2a = (const float*)d_in[9];
    const float* er2b = (const float*)d_in[10];
    const float* pw   = (const float*)d_in[11];
    const float* pb   = (const float*)d_in[12];
    const float* cbk  = (const float*)d_in[13];
    const float* dw1  = (const float*)d_in[14];
    const float* db1  = (const float*)d_in[15];
    const float* dr1a = (const float*)d_in[16];
    const float* dr1b = (const float*)d_in[17];
    const float* dr2a = (const float*)d_in[18];
    const float* dr2b = (const float*)d_in[19];
    const float* dtw1 = (const float*)d_in[20];
    const float* dtb1 = (const float*)d_in[21];
    const float* dtw2 = (const float*)d_in[22];
    const float* dtb2 = (const float*)d_in[23];

    float* out  = (float*)d_out;
    // output layout: [loss(1)][x_rec(16*1*256*256)][perplexity(1)][enc(65536*512)][quantized(16*64*64*64)]
    float* xrec = out + 1;
    float* perp = out + 1 + 1048576;
    float* enc  = out + 1048578;
    float* qout = out + 1048578 + 33554432;

    float *h1, *h2, *h3, *t32, *z, *d1, *dt1;
    cudaGetSymbolAddress((void**)&h1,  g_h1);
    cudaGetSymbolAddress((void**)&h2,  g_h2);
    cudaGetSymbolAddress((void**)&h3,  g_h3);
    cudaGetSymbolAddress((void**)&t32, g_t32);
    cudaGetSymbolAddress((void**)&z,   g_z);
    cudaGetSymbolAddress((void**)&d1,  g_d1);
    cudaGetSymbolAddress((void**)&dt1, g_dt1);

    const dim3 bq(32, 8);     // conv2 (2x2-px)
    const dim3 b2(64, 4);     // conv3x3 / 1x1 / convT1

    // ---- encoder ----
    k_conv1<<<dim3(64, 16), dim3(128, 2)>>>(x, ew1, eb1, h1);
    k_conv2<<<dim3(4, 16, 16), bq>>>(h1, ew2, eb2, h2);
    k_conv3x3<128, 128, false, true ><<<dim3(8, 8, 16), b2>>>(h2, ew3, eb3, h3);
    k_conv3x3<128,  32, true,  false><<<dim3(8, 2, 16), b2>>>(h3, er1a, (const float*)0, t32);
    k_conv1x1< 32, 128, true,  false, true,  false><<<dim3(8, 4, 16), b2>>>(t32, er1b, (const float*)0, h3, h3);
    k_conv3x3<128,  32, true,  false><<<dim3(8, 2, 16), b2>>>(h3, er2a, (const float*)0, t32);
    k_conv1x1< 32, 128, true,  false, true,  false><<<dim3(8, 4, 16), b2>>>(t32, er2b, (const float*)0, h3, h3);
    k_conv1x1<128,  64, true,  true,  false, true ><<<dim3(8, 2, 16), b2>>>(h3, pw, pb, (const float*)0, z);

    // ---- VQ ----
    cudaMemsetAsync(enc, 0, (size_t)33554432 * sizeof(float), 0);
    k_vq_prep<<<1, 512>>>(cbk);
    k_vq<<<256, 256>>>(cbk, qout, enc);
    k_finalize<<<1, 32>>>(out, perp);

    // ---- decoder ----
    k_conv3x3< 64, 128, false, true ><<<dim3(8, 8, 16), b2>>>(qout, dw1, db1, d1);
    k_conv3x3<128,  32, true,  false><<<dim3(8, 2, 16), b2>>>(d1, dr1a, (const float*)0, t32);
    k_conv1x1< 32, 128, true,  false, true,  false><<<dim3(8, 4, 16), b2>>>(t32, dr1b, (const float*)0, d1, d1);
    k_conv3x3<128,  32, true,  false><<<dim3(8, 2, 16), b2>>>(d1, dr2a, (const float*)0, t32);
    k_conv1x1< 32, 128, true,  false, true,  false><<<dim3(8, 4, 16), b2>>>(t32, dr2b, (const float*)0, d1, d1);
    k_convT1<<<dim3(16, 8, 16), b2>>>(d1, dtw1, dtb1, dt1);
    k_convT2<<<dim3(256, 16), 256>>>(dt1, dtw2, dtb2, xrec);
}

// round 16
// speedup vs baseline: 1.0333x; 1.0333x over previous
#include <cuda_runtime.h>
#include <math.h>

typedef unsigned long long u64;
#define DEV static __device__ __forceinline__

// ---------------- packed f32x2 helpers ----------------
DEV void fma2(u64 &d, u64 a, u64 b) {
    asm("fma.rn.f32x2 %0, %1, %2, %0;" : "+l"(d) : "l"(a), "l"(b));
}
DEV u64 bcast2(float x) {
    u64 r; asm("mov.b64 %0, {%1, %1};" : "=l"(r) : "f"(x)); return r;
}
DEV u64 pack2(float lo, float hi) {
    u64 r; asm("mov.b64 %0, {%1, %2};" : "=l"(r) : "f"(lo), "f"(hi)); return r;
}
DEV void unpack2(u64 v, float &a, float &b) {
    asm("mov.b64 {%0, %1}, %2;" : "=f"(a), "=f"(b) : "l"(v));
}

// ---------------- scratch (static device memory; no runtime allocs) ------
__device__ float g_h1 [16*64*128*128];   // encoder conv1 out
__device__ float g_h2 [16*128*64*64];    // encoder conv2 out
__device__ float g_h3 [16*128*64*64];    // conv3 / resblock io
__device__ float g_t32[16*32*64*64];     // resblock mid
__device__ float g_z  [16*64*64*64];     // pre-VQ latents, NHWC (pixel-major)
__device__ float g_d1 [16*128*64*64];    // decoder 128ch buffer
__device__ float g_dt1[16*64*128*128];   // convT1 out
__device__ float g_cnorm[512];
__device__ float g_bsums[256];
__device__ int   g_counts[512];

// ======================================================================
// conv1: x(16,1,256,256) -> h1(16,64,128,128), 4x4 s2 p1, bias+ReLU
// (unchanged — bit-exact encoder path)
// ======================================================================
__global__ void __launch_bounds__(256) k_conv1(
    const float* __restrict__ x, const float* __restrict__ w,
    const float* __restrict__ bias, float* __restrict__ out)
{
    const int X = threadIdx.x;
    const int Y = blockIdx.x * 2 + threadIdx.y;
    const int n = blockIdx.y;
    const int tid = threadIdx.y * 128 + X;

    __shared__ __align__(16) float ws[16 * 64];   // [tap][oc]
    for (int i = tid; i < 1024; i += 256) {
        int oc = i & 63, tap = i >> 6;
        ws[tap * 64 + oc] = w[oc * 16 + tap];
    }
    __syncthreads();

    u64 acc[32];
#pragma unroll
    for (int i = 0; i < 32; i++) acc[i] = 0ull;

    const float* xin = x + (size_t)n * 65536;
#pragma unroll
    for (int dy = 0; dy < 4; dy++) {
        int iy = 2 * Y + dy - 1;
        bool yv = (unsigned)iy < 256u;
#pragma unroll
        for (int dx = 0; dx < 4; dx++) {
            int ix = 2 * X + dx - 1;
            float v = (yv && (unsigned)ix < 256u) ? xin[iy * 256 + ix] : 0.f;
            u64 vb = bcast2(v);
            const ulonglong2* wp = (const ulonglong2*)&ws[(dy * 4 + dx) * 64];
#pragma unroll
            for (int j = 0; j < 16; j++) {
                ulonglong2 wv = wp[j];
                fma2(acc[2*j],   vb, wv.x);
                fma2(acc[2*j+1], vb, wv.y);
            }
        }
    }
    float* o = out + (((size_t)n * 64) * 128 + Y) * 128 + X;
#pragma unroll
    for (int j = 0; j < 32; j++) {
        float a, b; unpack2(acc[j], a, b);
        a = fmaxf(a + bias[2*j],   0.f);
        b = fmaxf(b + bias[2*j+1], 0.f);
        o[(2*j)   * 16384] = a;
        o[(2*j+1) * 16384] = b;
    }
}

// ======================================================================
// conv2: h1(16,64,128,128) -> h2(16,128,64,64), 4x4 s2 p1, bias+ReLU
// 2x2 output px per thread, OC_T=8.  blockDim(32,8)  grid(4, 16, 16)
// (kept from R14 — measured improvement)
// ======================================================================
__global__ void __launch_bounds__(256, 2) k_conv2(
    const float* __restrict__ in, const float* __restrict__ w,
    const float* __restrict__ bias, float* __restrict__ out)
{
    const int tx = threadIdx.x;                 // 0..31
    const int ty = threadIdx.y;                 // 0..7
    const int X0 = tx * 2;
    const int Y0 = blockIdx.x * 16 + ty * 2;
    const int ocB = blockIdx.y * 8;
    const int n = blockIdx.z;
    const int tid = ty * 32 + tx;

    __shared__ __align__(16) float ws[16 * 16 * 8];   // [cc][tap][oc8] = 2048

    u64 acc[4][4];                               // [qy*2+qx][oc-pair]
#pragma unroll
    for (int i = 0; i < 4; i++)
#pragma unroll
        for (int j = 0; j < 4; j++) acc[i][j] = 0ull;

    for (int cib = 0; cib < 64; cib += 16) {
        __syncthreads();
#pragma unroll
        for (int i = 0; i < 8; i++) {
            int idx = tid + i * 256;
            int oc = idx & 7, tap = (idx >> 3) & 15, cc = idx >> 7;
            ws[idx] = w[((ocB + oc) * 64 + cib + cc) * 16 + tap];
        }
        __syncthreads();
#pragma unroll 2
        for (int cc = 0; cc < 16; cc++) {
            const float* p = in + (size_t)(n * 64 + cib + cc) * 16384;
#pragma unroll
            for (int r = 0; r < 6; r++) {
                int iy = 2 * Y0 - 1 + r;
                bool yv = (unsigned)iy < 128u;
                const float* row = p + iy * 128 + 2 * X0 - 1;
                u64 vbr[6];
#pragma unroll
                for (int c = 0; c < 6; c++) {
                    int ix = 2 * X0 - 1 + c;
                    float v = (yv && (unsigned)ix < 128u) ? row[c] : 0.f;
                    vbr[c] = bcast2(v);
                }
#pragma unroll
                for (int qy = 0; qy < 2; qy++) {
                    int dy = r - 2 * qy;
                    if (dy < 0 || dy > 3) continue;
#pragma unroll
                    for (int dx = 0; dx < 4; dx++) {
                        const ulonglong2* wp = (const ulonglong2*)&ws[(cc * 16 + dy * 4 + dx) * 8];
                        ulonglong2 w0 = wp[0], w1 = wp[1];
#pragma unroll
                        for (int qx = 0; qx < 2; qx++) {
                            u64 b = vbr[dx + 2 * qx];
                            fma2(acc[qy*2+qx][0], b, w0.x);
                            fma2(acc[qy*2+qx][1], b, w0.y);
                            fma2(acc[qy*2+qx][2], b, w1.x);
                            fma2(acc[qy*2+qx][3], b, w1.y);
                        }
                    }
                }
            }
        }
    }
    float* o = out + ((size_t)(n * 128 + ocB)) * 4096 + Y0 * 64 + X0;
#pragma unroll
    for (int j = 0; j < 4; j++) {
        float q0 = bias[ocB + 2*j], q1 = bias[ocB + 2*j+1];
#pragma unroll
        for (int qy = 0; qy < 2; qy++)
#pragma unroll
            for (int qx = 0; qx < 2; qx++) {
                float a, b; unpack2(acc[qy*2+qx][j], a, b);
                o[(2*j)   * 4096 + qy * 64 + qx] = fmaxf(a + q0, 0.f);
                o[(2*j+1) * 4096 + qy * 64 + qx] = fmaxf(b + q1, 0.f);
            }
    }
}

// ======================================================================
// generic 3x3 conv on 64x64, stride1 pad1.  2 px/thread (Y0, Y0+4), OC_T=16.
// blockDim(64,4)  grid(8, COUT/16, 16)
// EXACT R12 body — measured 140us / fma 44.5% / issue 47%.  18 independent
// LDG per cc is what sustains MLP at the 16-warp occupancy cap.
// ======================================================================
template<int CIN, int COUT, bool RELU_IN, bool HAS_BIAS>
__global__ void __launch_bounds__(256, 2) k_conv3x3(
    const float* __restrict__ in, const float* __restrict__ w,
    const float* __restrict__ bias, float* __restrict__ out)
{
    const int X = threadIdx.x;
    const int Y0 = blockIdx.x * 8 + threadIdx.y;   // rows Y0, Y0+4
    const int ocB = blockIdx.y * 16;
    const int n = blockIdx.z;
    const int tid = threadIdx.y * 64 + X;

    __shared__ __align__(16) float ws[32 * 9 * 16];   // [cc][tap][oc16] = 4608

    u64 a0[8], a1[8];
#pragma unroll
    for (int i = 0; i < 8; i++) { a0[i] = 0ull; a1[i] = 0ull; }

    const bool xm = (X > 0), xp = (X < 63);
    for (int cib = 0; cib < CIN; cib += 32) {
        __syncthreads();
#pragma unroll
        for (int i = 0; i < 18; i++) {
            int idx = tid + i * 256;                  // < 4608
            int oc = idx & 15;
            int r  = idx >> 4;
            int tap = r % 9;
            int cc = r / 9;
            ws[(cc * 9 + tap) * 16 + oc] = w[((ocB + oc) * CIN + cib + cc) * 9 + tap];
        }
        __syncthreads();
#pragma unroll 2
        for (int cc = 0; cc < 32; cc++) {
            const float* p = in + (size_t)(n * CIN + cib + cc) * 4096;
            float v0[9], v1[9];
#pragma unroll
            for (int r = 0; r < 3; r++) {
                int iy0 = Y0 + r - 1;
                bool yv0 = (unsigned)iy0 < 64u;
                const float* row0 = p + iy0 * 64 + X;
                v0[r*3+0] = (yv0 && xm) ? row0[-1] : 0.f;
                v0[r*3+1] =  yv0        ? row0[0]  : 0.f;
                v0[r*3+2] = (yv0 && xp) ? row0[1]  : 0.f;
                int iy1 = iy0 + 4;
                bool yv1 = (unsigned)iy1 < 64u;
                const float* row1 = p + iy1 * 64 + X;
                v1[r*3+0] = (yv1 && xm) ? row1[-1] : 0.f;
                v1[r*3+1] =  yv1        ? row1[0]  : 0.f;
                v1[r*3+2] = (yv1 && xp) ? row1[1]  : 0.f;
            }
            if (RELU_IN) {
#pragma unroll
                for (int t = 0; t < 9; t++) {
                    v0[t] = fmaxf(v0[t], 0.f);
                    v1[t] = fmaxf(v1[t], 0.f);
                }
            }
#pragma unroll
            for (int t = 0; t < 9; t++) {
                u64 b0 = bcast2(v0[t]);
                u64 b1 = bcast2(v1[t]);
                const ulonglong2* wp = (const ulonglong2*)&ws[(cc * 9 + t) * 16];
#pragma unroll
                for (int j = 0; j < 4; j++) {
                    ulonglong2 wv = wp[j];
                    fma2(a0[2*j],   b0, wv.x);
                    fma2(a0[2*j+1], b0, wv.y);
                    fma2(a1[2*j],   b1, wv.x);
                    fma2(a1[2*j+1], b1, wv.y);
                }
            }
        }
    }
    float* o0 = out + ((size_t)(n * COUT + ocB)) * 4096 + Y0 * 64 + X;
    float* o1 = o0 + 4 * 64;
#pragma unroll
    for (int j = 0; j < 8; j++) {
        float a, b; unpack2(a0[j], a, b);
        float c, d; unpack2(a1[j], c, d);
        if (HAS_BIAS) {
            float p0 = bias[ocB + 2*j], p1 = bias[ocB + 2*j+1];
            a += p0; b += p1; c += p0; d += p1;
        }
        o0[(2*j)   * 4096] = a;
        o0[(2*j+1) * 4096] = b;
        o1[(2*j)   * 4096] = c;
        o1[(2*j+1) * 4096] = d;
    }
}

// ======================================================================
// generic 1x1 conv on 64x64.  2 px/thread, OC_T=32. (unchanged)
// blockDim(64,4)  grid(8, COUT/32, 16)
// ======================================================================
template<int CIN, int COUT, bool RELU_IN, bool HAS_BIAS, bool RESID, bool NHWC_OUT>
__global__ void __launch_bounds__(256, 2) k_conv1x1(
    const float* __restrict__ in, const float* __restrict__ w,
    const float* __restrict__ bias, const float* __restrict__ resid,
    float* __restrict__ out)
{
    const int X = threadIdx.x;
    const int Y0 = blockIdx.x * 8 + threadIdx.y;   // rows Y0, Y0+4
    const int ocB = blockIdx.y * 32;
    const int n = blockIdx.z;
    const int tid = threadIdx.y * 64 + X;

    __shared__ __align__(16) float ws[CIN * 32];
    for (int i = tid; i < CIN * 32; i += 256) {
        int oc = i & 31, c = i >> 5;
        ws[i] = w[(ocB + oc) * CIN + c];
    }
    __syncthreads();

    u64 a0[16], a1[16];
#pragma unroll
    for (int i = 0; i < 16; i++) { a0[i] = 0ull; a1[i] = 0ull; }

    const float* p0 = in + (size_t)n * CIN * 4096 + Y0 * 64 + X;
    const float* p1 = p0 + 4 * 64;
#pragma unroll 4
    for (int c = 0; c < CIN; c++) {
        float v0 = p0[c * 4096];
        float v1 = p1[c * 4096];
        if (RELU_IN) { v0 = fmaxf(v0, 0.f); v1 = fmaxf(v1, 0.f); }
        u64 b0 = bcast2(v0), b1 = bcast2(v1);
        const ulonglong2* wp = (const ulonglong2*)&ws[c * 32];
#pragma unroll
        for (int j = 0; j < 8; j++) {
            ulonglong2 wv = wp[j];
            fma2(a0[2*j],   b0, wv.x);
            fma2(a0[2*j+1], b0, wv.y);
            fma2(a1[2*j],   b1, wv.x);
            fma2(a1[2*j+1], b1, wv.y);
        }
    }
    if (NHWC_OUT) {
        float* o0 = out + ((size_t)((n * 64 + Y0) * 64 + X)) * COUT + ocB;
        float* o1 = o0 + (size_t)4 * 64 * COUT;
#pragma unroll
        for (int j = 0; j < 16; j++) {
            float a, b; unpack2(a0[j], a, b);
            float c, d; unpack2(a1[j], c, d);
            if (HAS_BIAS) {
                float q0 = bias[ocB + 2*j], q1 = bias[ocB + 2*j+1];
                a += q0; b += q1; c += q0; d += q1;
            }
            o0[2*j] = a; o0[2*j+1] = b;
            o1[2*j] = c; o1[2*j+1] = d;
        }
    } else {
        float* o0 = out + ((size_t)(n * COUT + ocB)) * 4096 + Y0 * 64 + X;
        float* o1 = o0 + 4 * 64;
        const float* r0 = RESID ? resid + ((size_t)(n * COUT + ocB)) * 4096 + Y0 * 64 + X : (const float*)0;
        const float* r1 = RESID ? r0 + 4 * 64 : (const float*)0;
#pragma unroll
        for (int j = 0; j < 16; j++) {
            float a, b; unpack2(a0[j], a, b);
            float c, d; unpack2(a1[j], c, d);
            if (HAS_BIAS) {
                float q0 = bias[ocB + 2*j], q1 = bias[ocB + 2*j+1];
                a += q0; b += q1; c += q0; d += q1;
            }
            if (RESID) {
                a += r0[(2*j) * 4096]; b += r0[(2*j+1) * 4096];
                c += r1[(2*j) * 4096]; d += r1[(2*j+1) * 4096];
            }
            o0[(2*j)   * 4096] = a;
            o0[(2*j+1) * 4096] = b;
            o1[(2*j)   * 4096] = c;
            o1[(2*j+1) * 4096] = d;
        }
    }
}

// ======================================================================
// XLA-GPU-style 64-element fp32 row sum of squares (reference-matching).
// ======================================================================
DEV float rowsumsq64(const float* __restrict__ x) {
    float p[32];
#pragma unroll
    for (int t = 0; t < 32; t++) {
        float m0 = __fmul_rn(x[2*t],   x[2*t]);
        float m1 = __fmul_rn(x[2*t+1], x[2*t+1]);
        p[t] = __fadd_rn(m0, m1);
    }
#pragma unroll
    for (int off = 16; off >= 1; off >>= 1) {
#pragma unroll
        for (int t = 0; t < 16; t++)
            if (t < off) p[t] = __fadd_rn(p[t], p[t + off]);
    }
    return p[0];
}

// ======================================================================
// VQ prep: codebook norms + zero reductions.  <<<1,512>>>
// ======================================================================
__global__ void k_vq_prep(const float* __restrict__ cb) {
    int t = threadIdx.x;
    float row[64];
    const float4* rp = (const float4*)(cb + t * 64);
#pragma unroll
    for (int i = 0; i < 16; i++) {
        float4 v = rp[i];
        row[4*i] = v.x; row[4*i+1] = v.y; row[4*i+2] = v.z; row[4*i+3] = v.w;
    }
    g_cnorm[t] = rowsumsq64(row);
    g_counts[t] = 0;
    if (t < 256) g_bsums[t] = 0.f;
}

// ======================================================================
// VQ main: one thread per pixel.  <<<256, 256>>>
// ======================================================================
__global__ void __launch_bounds__(256) k_vq(
    const float* __restrict__ cb, float* __restrict__ qout,
    float* __restrict__ enc)
{
    const int p = blockIdx.x * 256 + threadIdx.x;
    const int t = threadIdx.x;
    __shared__ __align__(16) float cbs[64 * 64];
    __shared__ float cns[64];
    __shared__ int hist[512];
    __shared__ float red[256];
    for (int i = t; i < 512; i += 256) hist[i] = 0;

    u64 zv[32];
    float zz;
    {
        float zrow[64];
        const float4* zp = (const float4*)(g_z + (size_t)p * 64);
#pragma unroll
        for (int i = 0; i < 16; i++) {
            float4 z4 = zp[i];
            zrow[4*i] = z4.x; zrow[4*i+1] = z4.y; zrow[4*i+2] = z4.z; zrow[4*i+3] = z4.w;
            zv[2*i]   = pack2(z4.x, z4.y);
            zv[2*i+1] = pack2(z4.z, z4.w);
        }
        zz = rowsumsq64(zrow);
    }

    float best = 3.4e38f; int bk = 0;
    for (int kb = 0; kb < 512; kb += 64) {
        __syncthreads();
        for (int i = t; i < 64 * 64; i += 256) cbs[i] = cb[kb * 64 + i];
        if (t < 64) cns[t] = g_cnorm[kb + t];
        __syncthreads();
#pragma unroll 2
        for (int kk = 0; kk < 64; kk++) {
            u64 s0 = 0ull, s1 = 0ull;
            const ulonglong2* cp = (const ulonglong2*)&cbs[kk * 64];
#pragma unroll
            for (int j = 0; j < 16; j++) {
                ulonglong2 cw = cp[j];
                fma2(s0, zv[2*j],   cw.x);
                fma2(s1, zv[2*j+1], cw.y);
            }
            float a, b, c, d; unpack2(s0, a, b); unpack2(s1, c, d);
            float dot = (a + b) + (c + d);
            float dist = __fsub_rn(__fadd_rn(zz, cns[kk]), 2.0f * dot);
            if (dist < best) { best = dist; bk = kb + kk; }
        }
    }

    const float* q = cb + bk * 64;
    const int n = p >> 12;
    const int yx = p & 4095;
    float* qo = qout + (size_t)n * 64 * 4096 + yx;
    float sse = 0.f;
#pragma unroll
    for (int i = 0; i < 16; i++) {
        float4 qv = ((const float4*)q)[i];
        float z0, z1, z2, z3;
        unpack2(zv[2*i], z0, z1); unpack2(zv[2*i+1], z2, z3);
        float d0 = qv.x - z0, d1 = qv.y - z1, d2 = qv.z - z2, d3 = qv.w - z3;
        sse += d0*d0 + d1*d1 + d2*d2 + d3*d3;
        qo[(4*i)   * 4096] = qv.x;
        qo[(4*i+1) * 4096] = qv.y;
        qo[(4*i+2) * 4096] = qv.z;
        qo[(4*i+3) * 4096] = qv.w;
    }
    enc[(size_t)p * 512 + bk] = 1.0f;
    atomicAdd(&hist[bk], 1);
    red[t] = sse;
    __syncthreads();
    for (int s = 128; s > 0; s >>= 1) {
        if (t < s) red[t] += red[t + s];
        __syncthreads();
    }
    if (t == 0) g_bsums[blockIdx.x] = red[0];
    for (int i = t; i < 512; i += 256)
        if (hist[i]) atomicAdd(&g_counts[i], hist[i]);
}

// ======================================================================
// finalize: loss + perplexity scalars
// ======================================================================
__global__ void k_finalize(float* __restrict__ out_loss, float* __restrict__ out_perp) {
    if (threadIdx.x == 0) {
        float s = 0.f;
        for (int i = 0; i < 256; i++) s += g_bsums[i];
        out_loss[0] = 1.25f * s / (65536.f * 64.f);
        float h = 0.f;
        for (int k = 0; k < 512; k++) {
            float avg = (float)g_counts[k] / 65536.f;
            h += avg * logf(avg + 1e-10f);
        }
        out_perp[0] = expf(-h);
    }
}

// ======================================================================
// convT1: d1(16,128,64,64) -> dt1(16,64,128,128), 4x4 s2 p1, bias+ReLU
// same-parity 2x2 px/thread (shares 4 taps + 3x3 input patch), OC_T=8.
// blockDim(64,4)  grid(16, 8, 16)   (kept from R14 — measured improvement)
// ======================================================================
__global__ void __launch_bounds__(256, 2) k_convT1(
    const float* __restrict__ in, const float* __restrict__ w,
    const float* __restrict__ bias, float* __restrict__ out)
{
    const int tx = threadIdx.x;                       // 0..63
    const int X0 = (tx & 1) | ((tx >> 1) << 2);       // cols X0, X0+2
    const int vv = blockIdx.x * 4 + threadIdx.y;      // 0..63
    const int Y0 = (vv & 1) | ((vv >> 1) << 2);       // rows Y0, Y0+2
    const int ocB = blockIdx.y * 8;
    const int n = blockIdx.z;
    const int tid = threadIdx.y * 64 + tx;

    __shared__ __align__(16) float ws[16 * 16 * 8];   // [cc][tap][oc8] = 2048

    int ys0, tys0, tys1;      // ys1 = ys0 - 1
    if (Y0 & 1) { ys0 = (Y0 + 1) >> 1; tys0 = 0; tys1 = 2; }
    else        { ys0 =  Y0      >> 1; tys0 = 1; tys1 = 3; }
    int xs0, txs0, txs1;      // xs1 = xs0 - 1
    if (X0 & 1) { xs0 = (X0 + 1) >> 1; txs0 = 0; txs1 = 2; }
    else        { xs0 =  X0      >> 1; txs0 = 1; txs1 = 3; }
    const int tys[2] = { tys0, tys1 };
    const int txs[2] = { txs0, txs1 };
    const int rbase = ys0 - 1;   // input rows rbase..rbase+2
    const int cbase = xs0 - 1;   // input cols cbase..cbase+2

    u64 acc[4][4];
#pragma unroll
    for (int i = 0; i < 4; i++)
#pragma unroll
        for (int j = 0; j < 4; j++) acc[i][j] = 0ull;

    for (int cib = 0; cib < 128; cib += 16) {
        __syncthreads();
#pragma unroll
        for (int i = 0; i < 8; i++) {
            int idx = tid + i * 256;
            int oc = idx & 7, tap = (idx >> 3) & 15, cc = idx >> 7;
            ws[idx] = w[((cib + cc) * 64 + ocB + oc) * 16 + tap];
        }
        __syncthreads();
#pragma unroll 2
        for (int cc = 0; cc < 16; cc++) {
            const float* p = in + (size_t)(n * 128 + cib + cc) * 4096;
            u64 vb[3][3];
#pragma unroll
            for (int r = 0; r < 3; r++) {
                int iy = rbase + r;
                bool yv = (unsigned)iy < 64u;
#pragma unroll
                for (int c = 0; c < 3; c++) {
                    int ix = cbase + c;
                    float v = (yv && (unsigned)ix < 64u) ? p[iy * 64 + ix] : 0.f;
                    vb[r][c] = bcast2(v);
                }
            }
#pragma unroll
            for (int a = 0; a < 2; a++) {
#pragma unroll
                for (int b = 0; b < 2; b++) {
                    int tap = tys[a] * 4 + txs[b];
                    const ulonglong2* wp = (const ulonglong2*)&ws[(cc * 16 + tap) * 8];
                    ulonglong2 w0 = wp[0], w1 = wp[1];
#pragma unroll
                    for (int qy = 0; qy < 2; qy++) {
#pragma unroll
                        for (int qx = 0; qx < 2; qx++) {
                            u64 bv = vb[1 - a + qy][1 - b + qx];
                            fma2(acc[qy*2+qx][0], bv, w0.x);
                            fma2(acc[qy*2+qx][1], bv, w0.y);
                            fma2(acc[qy*2+qx][2], bv, w1.x);
                            fma2(acc[qy*2+qx][3], bv, w1.y);
                        }
                    }
                }
            }
        }
    }
    float* o = out + ((size_t)(n * 64 + ocB)) * 16384 + Y0 * 128 + X0;
#pragma unroll
    for (int j = 0; j < 4; j++) {
        float q0 = bias[ocB + 2*j], q1 = bias[ocB + 2*j+1];
#pragma unroll
        for (int qy = 0; qy < 2; qy++)
#pragma unroll
            for (int qx = 0; qx < 2; qx++) {
                float a, b; unpack2(acc[qy*2+qx][j], a, b);
                o[(2*j)   * 16384 + qy * 2 * 128 + qx * 2] = fmaxf(a + q0, 0.f);
                o[(2*j+1) * 16384 + qy * 2 * 128 + qx * 2] = fmaxf(b + q1, 0.f);
            }
    }
}

// ======================================================================
// convT2: dt1(16,64,128,128) -> x_rec(16,1,256,256), 4x4 s2 p1, bias
// ======================================================================
__global__ void __launch_bounds__(256) k_convT2(
    const float* __restrict__ in, const float* __restrict__ w,
    const float* __restrict__ bias, float* __restrict__ out)
{
    const int X = threadIdx.x;
    const int Y = blockIdx.x;
    const int n = blockIdx.y;
    __shared__ float ws[1024];   // [tap][ci]
    for (int i = X; i < 1024; i += 256) {
        int tp = i >> 6, ci = i & 63;
        ws[tp * 64 + ci] = w[ci * 16 + tp];
    }
    __syncthreads();

    int ys[2], tys[2], xs[2], txs[2];
    if (Y & 1) { ys[0] = (Y+1) >> 1; tys[0] = 0; ys[1] = (Y-1) >> 1; tys[1] = 2; }
    else       { ys[0] =  Y    >> 1; tys[0] = 1; ys[1] = (Y-2) >> 1; tys[1] = 3; }
    if (X & 1) { xs[0] = (X+1) >> 1; txs[0] = 0; xs[1] = (X-1) >> 1; txs[1] = 2; }
    else       { xs[0] =  X    >> 1; txs[0] = 1; xs[1] = (X-2) >> 1; txs[1] = 3; }

    float acc = bias[0];
#pragma unroll
    for (int a = 0; a < 2; a++) {
        if ((unsigned)ys[a] >= 128u) continue;
#pragma unroll
        for (int b = 0; b < 2; b++) {
            if ((unsigned)xs[b] >= 128u) continue;
            const float* p = in + (size_t)n * 1048576 + ys[a] * 128 + xs[b];
            const float* wr = &ws[(tys[a] * 4 + txs[b]) * 64];
            float s = 0.f;
#pragma unroll 16
            for (int ci = 0; ci < 64; ci++) s += p[ci * 16384] * wr[ci];
            acc += s;
        }
    }
    out[(size_t)n * 65536 + Y * 256 + X] = acc;
}

// ======================================================================
// kernel_launch
// ======================================================================
extern "C" void kernel_launch(void* const* d_in, const int* in_sizes, int n_in,
                              void* d_out, int out_size)
{
    (void)in_sizes; (void)n_in; (void)out_size;
    const float* x    = (const float*)d_in[0];
    const float* ew1  = (const float*)d_in[1];
    const float* eb1  = (const float*)d_in[2];
    const float* ew2  = (const float*)d_in[3];
    const float* eb2  = (const float*)d_in[4];
    const float* ew3  = (const float*)d_in[5];
    const float* eb3  = (const float*)d_in[6];
    const float* er1a = (const float*)d_in[7];
    const float* er1b = (const float*)d_in[8];
    const float* er2a = (const float*)d_in[9];
    const float* er2b = (const float*)d_in[10];
    const float* pw   = (const float*)d_in[11];
    const float* pb   = (const float*)d_in[12];
    const float* cbk  = (const float*)d_in[13];
    const float* dw1  = (const float*)d_in[14];
    const float* db1  = (const float*)d_in[15];
    const float* dr1a = (const float*)d_in[16];
    const float* dr1b = (const float*)d_in[17];
    const float* dr2a = (const float*)d_in[18];
    const float* dr2b = (const float*)d_in[19];
    const float* dtw1 = (const float*)d_in[20];
    const float* dtb1 = (const float*)d_in[21];
    const float* dtw2 = (const float*)d_in[22];
    const float* dtb2 = (const float*)d_in[23];

    float* out  = (float*)d_out;
    // output layout: [loss(1)][x_rec(16*1*256*256)][perplexity(1)][enc(65536*512)][quantized(16*64*64*64)]
    float* xrec = out + 1;
    float* perp = out + 1 + 1048576;
    float* enc  = out + 1048578;
    float* qout = out + 1048578 + 33554432;

    float *h1, *h2, *h3, *t32, *z, *d1, *dt1;
    cudaGetSymbolAddress((void**)&h1,  g_h1);
    cudaGetSymbolAddress((void**)&h2,  g_h2);
    cudaGetSymbolAddress((void**)&h3,  g_h3);
    cudaGetSymbolAddress((void**)&t32, g_t32);
    cudaGetSymbolAddress((void**)&z,   g_z);
    cudaGetSymbolAddress((void**)&d1,  g_d1);
    cudaGetSymbolAddress((void**)&dt1, g_dt1);

    const dim3 bq(32, 8);     // conv2 (2x2-px)
    const dim3 b2(64, 4);     // conv3x3 / 1x1 / convT1

    // ---- encoder ----
    k_conv1<<<dim3(64, 16), dim3(128, 2)>>>(x, ew1, eb1, h1);
    k_conv2<<<dim3(4, 16, 16), bq>>>(h1, ew2, eb2, h2);
    k_conv3x3<128, 128, false, true ><<<dim3(8, 8, 16), b2>>>(h2, ew3, eb3, h3);
    k_conv3x3<128,  32, true,  false><<<dim3(8, 2, 16), b2>>>(h3, er1a, (const float*)0, t32);
    k_conv1x1< 32, 128, true,  false, true,  false><<<dim3(8, 4, 16), b2>>>(t32, er1b, (const float*)0, h3, h3);
    k_conv3x3<128,  32, true,  false><<<dim3(8, 2, 16), b2>>>(h3, er2a, (const float*)0, t32);
    k_conv1x1< 32, 128, true,  false, true,  false><<<dim3(8, 4, 16), b2>>>(t32, er2b, (const float*)0, h3, h3);
    k_conv1x1<128,  64, true,  true,  false, true ><<<dim3(8, 2, 16), b2>>>(h3, pw, pb, (const float*)0, z);

    // ---- VQ ----
    cudaMemsetAsync(enc, 0, (size_t)33554432 * sizeof(float), 0);
    k_vq_prep<<<1, 512>>>(cbk);
    k_vq<<<256, 256>>>(cbk, qout, enc);
    k_finalize<<<1, 32>>>(out, perp);

    // ---- decoder ----
    k_conv3x3< 64, 128, false, true ><<<dim3(8, 8, 16), b2>>>(qout, dw1, db1, d1);
    k_conv3x3<128,  32, true,  false><<<dim3(8, 2, 16), b2>>>(d1, dr1a, (const float*)0, t32);
    k_conv1x1< 32, 128, true,  false, true,  false><<<dim3(8, 4, 16), b2>>>(t32, dr1b, (const float*)0, d1, d1);
    k_conv3x3<128,  32, true,  false><<<dim3(8, 2, 16), b2>>>(d1, dr2a, (const float*)0, t32);
    k_conv1x1< 32, 128, true,  false, true,  false><<<dim3(8, 4, 16), b2>>>(t32, dr2b, (const float*)0, d1, d1);
    k_convT1<<<dim3(16, 8, 16), b2>>>(d1, dtw1, dtb1, dt1);
    k_convT2<<<dim3(256, 16), 256>>>(dt1, dtw2, dtb2, xrec);
}